// round 13
// baseline (speedup 1.0000x reference)
#include <cuda_runtime.h>

// HybridLoss: smooth_l1(preds,targets) + 0.5*(1 - mean(box_overlap))
// preds, targets: [2000000, 10] float32 row-major. Output: 1 float scalar.
//
// Persistent 1-wave kernel (740 CTAs x 256 thr, 5 CTA/SM), distance-1
// register prefetch. 10 guard-free full iterations + balanced tail
// (~143 rows/CTA). Occupancy experiment: 51-reg cap for 36 warps/SM.

#define NROWS 2000000
#define THREADS 256
#define NBLOCKS 740                                   // 148 SMs * 5 CTAs
#define TOTALT (NBLOCKS * THREADS)                    // 189,440
#define ITERS_FULL 10                                 // 10*189440 = 1,894,400
#define TAIL_START (ITERS_FULL * TOTALT)
#define TAIL (NROWS - TAIL_START)                     // 105,600
#define EPSF 1e-6f

__device__ double g_acc[2] = {0.0, 0.0};
__device__ unsigned int g_ticket = 0;

__device__ __forceinline__ void load_row(const float2* __restrict__ p2,
                                         const float2* __restrict__ t2,
                                         int row, float2* bp, float2* bt)
{
    const float2* rp = p2 + (size_t)row * 5;   // 40B rows -> 5 float2
    const float2* rt = t2 + (size_t)row * 5;
    #pragma unroll
    for (int j = 0; j < 5; j++) { bp[j] = rp[j]; bt[j] = rt[j]; }
}

__device__ __forceinline__ void row_math(const float2* __restrict__ bp,
                                         const float2* __restrict__ bt,
                                         float& l1_acc, float& ov_acc)
{
    float p[10], t[10];
    #pragma unroll
    for (int j = 0; j < 5; j++) {
        p[2*j] = bp[j].x; p[2*j+1] = bp[j].y;
        t[2*j] = bt[j].x; t[2*j+1] = bt[j].y;
    }

    // smooth L1, select-free
    #pragma unroll
    for (int j = 0; j < 10; j++) {
        float d  = p[j] - t[j];
        float ad = fabsf(d);
        float m  = fminf(ad, 1.0f);
        l1_acc = fmaf(m, fmaf(-0.5f, m, ad), l1_acc);
    }

    // raw quaternions (no normalization)
    const float px = p[6], py = p[7], pz = p[8], pw = p[9];
    const float gx = t[6], gy = t[7], gz = t[8], gw = t[9];
    const float Ap = px*px + py*py + pz*pz + pw*pw;
    const float Ag = gx*gx + gy*gy + gz*gz + gw*gw;
    const float rpg = __fdividef(1.0f, Ap * Ag);
    const float sp  = 0.5f * Ag * rpg;   // 0.5/Ap
    const float sg  = 0.5f * Ap * rpg;   // 0.5/Ag

    const float dq = px*gx + py*gy + pz*gz + pw*gw;
    const float rot_align = fmaxf(fmaf(4.0f * dq * dq, rpg, -1.0f) * (1.0f/3.0f), 0.0f);

    const float dpx = p[3], dpy = p[4], dpz = p[5];
    const float dgx = t[3], dgy = t[4], dgz = t[5];

    float num = 1.0f, den = 1.0f;
    {
        float mp = (Ap - 2.0f*(py*py + pz*pz))*dpx + 2.0f*(px*py + pz*pw)*dpy + 2.0f*(px*pz - py*pw)*dpz;
        float mg = (Ag - 2.0f*(gy*gy + gz*gz))*dgx + 2.0f*(gx*gy + gz*gw)*dgy + 2.0f*(gx*gz - gy*gw)*dgz;
        float pe = sp * fabsf(mp), ge = sg * fabsf(mg);
        float cd = fabsf(p[0] - t[0]);
        num *= fmaxf(2.0f * fminf(pe, ge) - cd, 0.0f);
        den *= pe + ge + EPSF;
    }
    {
        float mp = 2.0f*(px*py - pz*pw)*dpx + (Ap - 2.0f*(px*px + pz*pz))*dpy + 2.0f*(py*pz + px*pw)*dpz;
        float mg = 2.0f*(gx*gy - gz*gw)*dgx + (Ag - 2.0f*(gx*gx + gz*gz))*dgy + 2.0f*(gy*gz + gx*gw)*dgz;
        float pe = sp * fabsf(mp), ge = sg * fabsf(mg);
        float cd = fabsf(p[1] - t[1]);
        num *= fmaxf(2.0f * fminf(pe, ge) - cd, 0.0f);
        den *= pe + ge + EPSF;
    }
    {
        float mp = 2.0f*(px*pz + py*pw)*dpx + 2.0f*(py*pz - px*pw)*dpy + (Ap - 2.0f*(px*px + py*py))*dpz;
        float mg = 2.0f*(gx*gz + gy*gw)*dgx + 2.0f*(gy*gz - gx*gw)*dgy + (Ag - 2.0f*(gx*gx + gy*gy))*dgz;
        float pe = sp * fabsf(mp), ge = sg * fabsf(mg);
        float cd = fabsf(p[2] - t[2]);
        num *= fmaxf(2.0f * fminf(pe, ge) - cd, 0.0f);
        den *= pe + ge + EPSF;
    }
    ov_acc += __fdividef(num * rot_align, den);
}

__global__ __launch_bounds__(THREADS, 5) void hl_fused_kernel(
    const float* __restrict__ preds,
    const float* __restrict__ targets,
    float* __restrict__ out)
{
    const int tid  = threadIdx.x;
    const int bid  = blockIdx.x;
    const int row0 = bid * THREADS + tid;

    const float2* __restrict__ p2 = reinterpret_cast<const float2*>(preds);
    const float2* __restrict__ t2 = reinterpret_cast<const float2*>(targets);

    float l1_sum = 0.0f;
    float ov     = 0.0f;

    // prologue: regs for it=0
    float2 cp[5], ct[5];
    load_row(p2, t2, row0, cp, ct);

    // guard-free full iterations, distance-1 register prefetch
    #pragma unroll 1
    for (int it = 0; it < ITERS_FULL - 1; it++) {
        float2 np[5], nt[5];
        load_row(p2, t2, row0 + (it + 1) * TOTALT, np, nt);   // prefetch next
        row_math(cp, ct, l1_sum, ov);                          // compute current
        #pragma unroll
        for (int j = 0; j < 5; j++) { cp[j] = np[j]; ct[j] = nt[j]; }
    }
    // last full iteration: prefetch this thread's tail row (if any) instead
    {
        const int s = (int)(((long)bid * TAIL) / NBLOCKS);
        const int e = (int)(((long)(bid + 1) * TAIL) / NBLOCKS);
        const bool has_tail = tid < (e - s);

        float2 tp[5], tt[5];
        if (has_tail)
            load_row(p2, t2, TAIL_START + s + tid, tp, tt);

        row_math(cp, ct, l1_sum, ov);                          // final full iter

        if (has_tail)
            row_math(tp, tt, l1_sum, ov);                      // balanced tail
    }

    // ---- block reduction ----
    #pragma unroll
    for (int off = 16; off > 0; off >>= 1) {
        l1_sum += __shfl_down_sync(0xFFFFFFFFu, l1_sum, off);
        ov     += __shfl_down_sync(0xFFFFFFFFu, ov, off);
    }
    __shared__ float warp_l1[THREADS / 32];
    __shared__ float warp_ov[THREADS / 32];
    const int lane = tid & 31;
    const int wid  = tid >> 5;
    if (lane == 0) { warp_l1[wid] = l1_sum; warp_ov[wid] = ov; }
    __syncthreads();

    if (wid == 0) {
        float a = (lane < THREADS / 32) ? warp_l1[lane] : 0.0f;
        float b = (lane < THREADS / 32) ? warp_ov[lane] : 0.0f;
        #pragma unroll
        for (int off = 4; off > 0; off >>= 1) {
            a += __shfl_down_sync(0xFFFFFFFFu, a, off);
            b += __shfl_down_sync(0xFFFFFFFFu, b, off);
        }
        if (lane == 0) {
            atomicAdd(&g_acc[0], (double)a);
            atomicAdd(&g_acc[1], (double)b);
            __threadfence();
            unsigned int ticket = atomicAdd(&g_ticket, 1u);
            if (ticket == (unsigned int)(NBLOCKS - 1)) {
                double s0 = *((volatile double*)&g_acc[0]);
                double s1 = *((volatile double*)&g_acc[1]);
                double param_loss = s0 / ((double)NROWS * 10.0);
                double mean_ov    = s1 / (double)NROWS;
                out[0] = (float)(param_loss + 0.5 * (1.0 - mean_ov));
                *((volatile double*)&g_acc[0]) = 0.0;
                *((volatile double*)&g_acc[1]) = 0.0;
                __threadfence();
                g_ticket = 0;
                __threadfence();
            }
        }
    }
}

extern "C" void kernel_launch(void* const* d_in, const int* in_sizes, int n_in,
                              void* d_out, int out_size) {
    const float* preds   = (const float*)d_in[0];
    const float* targets = (const float*)d_in[1];
    float* out = (float*)d_out;

    hl_fused_kernel<<<NBLOCKS, THREADS>>>(preds, targets, out);
}

// round 14
// speedup vs baseline: 1.0589x; 1.0589x over previous
#include <cuda_runtime.h>

// HybridLoss: smooth_l1(preds,targets) + 0.5*(1 - mean(box_overlap))
// preds, targets: [2000000, 10] float32 row-major. Output: 1 float scalar.
//
// Persistent 1-wave kernel (592 CTAs x 256 thr, 4 CTA/SM), distance-1
// register prefetch, 13 guard-free iterations + balanced tail (R12 shape).
// NEW: streaming loads (ld.global.cs) — read-once data, evict-first policy.

#define NROWS 2000000
#define THREADS 256
#define NBLOCKS 592                                   // 148 SMs * 4 CTAs
#define TOTALT (NBLOCKS * THREADS)                    // 151,552
#define ITERS_FULL 13                                 // 13*151552 = 1,970,176
#define TAIL_START (ITERS_FULL * TOTALT)
#define TAIL (NROWS - TAIL_START)                     // 29,824
#define EPSF 1e-6f

__device__ double g_acc[2] = {0.0, 0.0};
__device__ unsigned int g_ticket = 0;

__device__ __forceinline__ float2 ldcs_f2(const float2* p) {
    float2 v;
    asm volatile("ld.global.cs.v2.f32 {%0, %1}, [%2];"
                 : "=f"(v.x), "=f"(v.y) : "l"(p));
    return v;
}

__device__ __forceinline__ void load_row(const float2* __restrict__ p2,
                                         const float2* __restrict__ t2,
                                         int row, float2* bp, float2* bt)
{
    const float2* rp = p2 + (size_t)row * 5;   // 40B rows -> 5 float2
    const float2* rt = t2 + (size_t)row * 5;
    #pragma unroll
    for (int j = 0; j < 5; j++) { bp[j] = ldcs_f2(rp + j); bt[j] = ldcs_f2(rt + j); }
}

__device__ __forceinline__ void row_math(const float2* __restrict__ bp,
                                         const float2* __restrict__ bt,
                                         float& l1_acc, float& ov_acc)
{
    float p[10], t[10];
    #pragma unroll
    for (int j = 0; j < 5; j++) {
        p[2*j] = bp[j].x; p[2*j+1] = bp[j].y;
        t[2*j] = bt[j].x; t[2*j+1] = bt[j].y;
    }

    // smooth L1, select-free
    #pragma unroll
    for (int j = 0; j < 10; j++) {
        float d  = p[j] - t[j];
        float ad = fabsf(d);
        float m  = fminf(ad, 1.0f);
        l1_acc = fmaf(m, fmaf(-0.5f, m, ad), l1_acc);
    }

    // raw quaternions (no normalization)
    const float px = p[6], py = p[7], pz = p[8], pw = p[9];
    const float gx = t[6], gy = t[7], gz = t[8], gw = t[9];
    const float Ap = px*px + py*py + pz*pz + pw*pw;
    const float Ag = gx*gx + gy*gy + gz*gz + gw*gw;
    const float rpg = __fdividef(1.0f, Ap * Ag);
    const float sp  = 0.5f * Ag * rpg;   // 0.5/Ap
    const float sg  = 0.5f * Ap * rpg;   // 0.5/Ag

    const float dq = px*gx + py*gy + pz*gz + pw*gw;
    const float rot_align = fmaxf(fmaf(4.0f * dq * dq, rpg, -1.0f) * (1.0f/3.0f), 0.0f);

    const float dpx = p[3], dpy = p[4], dpz = p[5];
    const float dgx = t[3], dgy = t[4], dgz = t[5];

    float num = 1.0f, den = 1.0f;
    {
        float mp = (Ap - 2.0f*(py*py + pz*pz))*dpx + 2.0f*(px*py + pz*pw)*dpy + 2.0f*(px*pz - py*pw)*dpz;
        float mg = (Ag - 2.0f*(gy*gy + gz*gz))*dgx + 2.0f*(gx*gy + gz*gw)*dgy + 2.0f*(gx*gz - gy*gw)*dgz;
        float pe = sp * fabsf(mp), ge = sg * fabsf(mg);
        float cd = fabsf(p[0] - t[0]);
        num *= fmaxf(2.0f * fminf(pe, ge) - cd, 0.0f);
        den *= pe + ge + EPSF;
    }
    {
        float mp = 2.0f*(px*py - pz*pw)*dpx + (Ap - 2.0f*(px*px + pz*pz))*dpy + 2.0f*(py*pz + px*pw)*dpz;
        float mg = 2.0f*(gx*gy - gz*gw)*dgx + (Ag - 2.0f*(gx*gx + gz*gz))*dgy + 2.0f*(gy*gz + gx*gw)*dgz;
        float pe = sp * fabsf(mp), ge = sg * fabsf(mg);
        float cd = fabsf(p[1] - t[1]);
        num *= fmaxf(2.0f * fminf(pe, ge) - cd, 0.0f);
        den *= pe + ge + EPSF;
    }
    {
        float mp = 2.0f*(px*pz + py*pw)*dpx + 2.0f*(py*pz - px*pw)*dpy + (Ap - 2.0f*(px*px + py*py))*dpz;
        float mg = 2.0f*(gx*gz + gy*gw)*dgx + 2.0f*(gy*gz - gx*gw)*dgy + (Ag - 2.0f*(gx*gx + gy*gy))*dgz;
        float pe = sp * fabsf(mp), ge = sg * fabsf(mg);
        float cd = fabsf(p[2] - t[2]);
        num *= fmaxf(2.0f * fminf(pe, ge) - cd, 0.0f);
        den *= pe + ge + EPSF;
    }
    ov_acc += __fdividef(num * rot_align, den);
}

__global__ __launch_bounds__(THREADS, 4) void hl_fused_kernel(
    const float* __restrict__ preds,
    const float* __restrict__ targets,
    float* __restrict__ out)
{
    const int tid  = threadIdx.x;
    const int bid  = blockIdx.x;
    const int row0 = bid * THREADS + tid;

    const float2* __restrict__ p2 = reinterpret_cast<const float2*>(preds);
    const float2* __restrict__ t2 = reinterpret_cast<const float2*>(targets);

    float l1_sum = 0.0f;
    float ov     = 0.0f;

    // prologue: regs for it=0
    float2 cp[5], ct[5];
    load_row(p2, t2, row0, cp, ct);

    // 13 guard-free full iterations, distance-1 register prefetch
    #pragma unroll 1
    for (int it = 0; it < ITERS_FULL - 1; it++) {
        float2 np[5], nt[5];
        load_row(p2, t2, row0 + (it + 1) * TOTALT, np, nt);   // prefetch next
        row_math(cp, ct, l1_sum, ov);                          // compute current
        #pragma unroll
        for (int j = 0; j < 5; j++) { cp[j] = np[j]; ct[j] = nt[j]; }
    }
    // last full iteration: prefetch this thread's tail row (if any) instead
    {
        const int s = (int)(((long)bid * TAIL) / NBLOCKS);
        const int e = (int)(((long)(bid + 1) * TAIL) / NBLOCKS);
        const bool has_tail = tid < (e - s);

        float2 tp[5], tt[5];
        if (has_tail)
            load_row(p2, t2, TAIL_START + s + tid, tp, tt);

        row_math(cp, ct, l1_sum, ov);                          // iteration 12

        if (has_tail)
            row_math(tp, tt, l1_sum, ov);                      // balanced tail
    }

    // ---- block reduction ----
    #pragma unroll
    for (int off = 16; off > 0; off >>= 1) {
        l1_sum += __shfl_down_sync(0xFFFFFFFFu, l1_sum, off);
        ov     += __shfl_down_sync(0xFFFFFFFFu, ov, off);
    }
    __shared__ float warp_l1[THREADS / 32];
    __shared__ float warp_ov[THREADS / 32];
    const int lane = tid & 31;
    const int wid  = tid >> 5;
    if (lane == 0) { warp_l1[wid] = l1_sum; warp_ov[wid] = ov; }
    __syncthreads();

    if (wid == 0) {
        float a = (lane < THREADS / 32) ? warp_l1[lane] : 0.0f;
        float b = (lane < THREADS / 32) ? warp_ov[lane] : 0.0f;
        #pragma unroll
        for (int off = 4; off > 0; off >>= 1) {
            a += __shfl_down_sync(0xFFFFFFFFu, a, off);
            b += __shfl_down_sync(0xFFFFFFFFu, b, off);
        }
        if (lane == 0) {
            atomicAdd(&g_acc[0], (double)a);
            atomicAdd(&g_acc[1], (double)b);
            __threadfence();
            unsigned int ticket = atomicAdd(&g_ticket, 1u);
            if (ticket == (unsigned int)(NBLOCKS - 1)) {
                double s0 = *((volatile double*)&g_acc[0]);
                double s1 = *((volatile double*)&g_acc[1]);
                double param_loss = s0 / ((double)NROWS * 10.0);
                double mean_ov    = s1 / (double)NROWS;
                out[0] = (float)(param_loss + 0.5 * (1.0 - mean_ov));
                *((volatile double*)&g_acc[0]) = 0.0;
                *((volatile double*)&g_acc[1]) = 0.0;
                __threadfence();
                g_ticket = 0;
                __threadfence();
            }
        }
    }
}

extern "C" void kernel_launch(void* const* d_in, const int* in_sizes, int n_in,
                              void* d_out, int out_size) {
    const float* preds   = (const float*)d_in[0];
    const float* targets = (const float*)d_in[1];
    float* out = (float*)d_out;

    hl_fused_kernel<<<NBLOCKS, THREADS>>>(preds, targets, out);
}